// round 9
// baseline (speedup 1.0000x reference)
#include <cuda_runtime.h>
#include <cuda_fp16.h>
#include <cstdint>

// B=4, H=16, S=1024, D=64 fp32. out buffer: out [B,H,S,D] then attn [B,H,S,S]
#define SEQ 1024
#define DH  64
#define BM  128
#define TPB 256
#define NCHUNK 8

// smem word offsets
#define KVF_W 0        // K frags [16nt][4ks][32][4] / V frags [8nt][8ks][32][4] = 8192 w
#define MFL_W 8192     // mask flags [1024]
#define RED_W 9216     // per-wc (m,l) float2 [2][128] = 512 w
#define RST_W 9728     // rowstat (m, 1/l) float2 [128] = 256 w
#define CSM_W 9984     // per-32col-group m_c -> corr factor [32][128] = 4096 w
#define SM_WORDS 14080
#define SM_BYTES (SM_WORDS * 4)

__device__ __forceinline__ uint32_t hpack(float lo, float hi) {
    uint32_t u;
    asm("cvt.rn.f16x2.f32 %0, %1, %2;" : "=r"(u) : "f"(hi), "f"(lo));
    return u;
}
__device__ __forceinline__ float hhi(float x) {
    return __half2float(__float2half_rn(x));
}
__device__ __forceinline__ void mma_f16(float* d, uint32_t a0, uint32_t a1,
                                        uint32_t a2, uint32_t a3,
                                        uint32_t b0, uint32_t b1) {
    asm volatile(
        "mma.sync.aligned.m16n8k16.row.col.f32.f16.f16.f32 "
        "{%0,%1,%2,%3},{%4,%5,%6,%7},{%8,%9},{%0,%1,%2,%3};"
        : "+f"(d[0]), "+f"(d[1]), "+f"(d[2]), "+f"(d[3])
        : "r"(a0), "r"(a1), "r"(a2), "r"(a3), "r"(b0), "r"(b1));
}

__global__ __launch_bounds__(TPB, 2)
void attn_fp16_kernel(const float* __restrict__ q,
                      const float* __restrict__ k,
                      const float* __restrict__ v,
                      const float* __restrict__ add_attn,
                      const int*   __restrict__ mask,
                      float* __restrict__ out,
                      float* __restrict__ attn)
{
    extern __shared__ uint32_t smw[];
    float* smf = reinterpret_cast<float*>(smw);

    const int tid  = threadIdx.x;
    const int w    = tid >> 5;
    const int lane = tid & 31;
    const int g    = lane >> 2;
    const int tig  = lane & 3;
    const int wr   = w >> 1;            // pass A: row group (32 rows)
    const int wc   = w & 1;             // pass A: key slot within sweep
    const int bh   = blockIdx.y;
    const int b    = bh >> 4;
    const int q0   = blockIdx.x * BM;
    const int r0   = wr * 32;

    const float* qbase = q + ((size_t)bh * SEQ + q0) * DH;
    const float* kbase = k + (size_t)bh * SEQ * DH;
    const float* vbase = v + (size_t)bh * SEQ * DH;
    const float* bias0 = add_attn + (size_t)b * SEQ * SEQ + (size_t)q0 * SEQ;
    float* attn0 = attn + ((size_t)bh * SEQ + q0) * SEQ;

    // ---- mask flags ----
    for (int i = tid; i < SEQ; i += TPB)
        smf[MFL_W + i] = mask[b * SEQ + i] ? 1.0f : 0.0f;

    // ---- Q hi A-fragments in regs (M=32: 2 row-blocks), fp16, scale folded ----
    uint4 qh[2][4];
    #pragma unroll
    for (int mt = 0; mt < 2; ++mt) {
        const float* qr0 = qbase + (size_t)(r0 + mt * 16 + g) * DH;
        const float* qr1 = qr0 + (size_t)8 * DH;
        #pragma unroll
        for (int ks = 0; ks < 4; ++ks) {
            float2 x0 = *(const float2*)(qr0 + ks * 16 + 2 * tig);
            float2 x1 = *(const float2*)(qr1 + ks * 16 + 2 * tig);
            float2 x2 = *(const float2*)(qr0 + ks * 16 + 2 * tig + 8);
            float2 x3 = *(const float2*)(qr1 + ks * 16 + 2 * tig + 8);
            qh[mt][ks].x = hpack(hhi(x0.x * 0.125f), hhi(x0.y * 0.125f));
            qh[mt][ks].y = hpack(hhi(x1.x * 0.125f), hhi(x1.y * 0.125f));
            qh[mt][ks].z = hpack(hhi(x2.x * 0.125f), hhi(x2.y * 0.125f));
            qh[mt][ks].w = hpack(hhi(x3.x * 0.125f), hhi(x3.y * 0.125f));
        }
    }

    // om uniform across tig lanes; ol per-lane
    float om[2][2], ol[2][2];
    #pragma unroll
    for (int mt = 0; mt < 2; ++mt)
        #pragma unroll
        for (int h = 0; h < 2; ++h) { om[mt][h] = -3.0e38f; ol[mt][h] = 0.0f; }

    // ========== Pass A: S = QK^T + bias, masked; e = exp(s - m_c) -> attn ====
    for (int ct = 0; ct < NCHUNK; ++ct) {
        __syncthreads();
        // stage K chunk: direct B-frag build, 1 STS.128 per task
        #pragma unroll
        for (int i = 0; i < 8; ++i) {
            int task = i * TPB + tid;
            int lt = task & 31, ks = (task >> 5) & 3, nt = task >> 7;
            int gt = lt >> 2, tt = lt & 3;
            const float* kp = kbase + (size_t)(ct * 128 + nt * 8 + gt) * DH
                            + ks * 16 + 2 * tt;
            float2 k01 = *(const float2*)kp;
            float2 k89 = *(const float2*)(kp + 8);
            float h0 = hhi(k01.x), h1 = hhi(k01.y);
            float h8 = hhi(k89.x), h9 = hhi(k89.y);
            uint4 u;
            u.x = hpack(h0, h1);
            u.y = hpack(h8, h9);
            u.z = hpack(k01.x - h0, k01.y - h1);
            u.w = hpack(k89.x - h8, k89.y - h9);
            *(uint4*)&smw[KVF_W + (uint32_t)(((nt * 4 + ks) * 32 + lt) * 4)] = u;
        }
        __syncthreads();

        // two 64-key sweeps; warp handles 32 keys (4 nt) per sweep
        #pragma unroll 1
        for (int s2 = 0; s2 < 2; ++s2) {
            const int ntb = s2 * 8 + wc * 4;
            const int cidx = ct * 4 + s2 * 2 + wc;
            float sacc[2][4][4];
            #pragma unroll
            for (int mt = 0; mt < 2; ++mt)
                #pragma unroll
                for (int ntl = 0; ntl < 4; ++ntl)
                    #pragma unroll
                    for (int r2 = 0; r2 < 4; ++r2) sacc[mt][ntl][r2] = 0.0f;

            #pragma unroll
            for (int ks = 0; ks < 4; ++ks)
                #pragma unroll
                for (int ntl = 0; ntl < 4; ++ntl) {
                    uint4 bb = *(const uint4*)&smw[KVF_W +
                        (uint32_t)((((ntb + ntl) * 4 + ks) * 32 + lane) * 4)];
                    #pragma unroll
                    for (int mt = 0; mt < 2; ++mt) {
                        mma_f16(sacc[mt][ntl], qh[mt][ks].x, qh[mt][ks].y,
                                qh[mt][ks].z, qh[mt][ks].w, bb.x, bb.y);
                        mma_f16(sacc[mt][ntl], qh[mt][ks].x, qh[mt][ks].y,
                                qh[mt][ks].z, qh[mt][ks].w, bb.z, bb.w);
                    }
                }

            // epilogue: bias + mask -> s (in sacc); row-uniform m; e -> attn
            #pragma unroll
            for (int mt = 0; mt < 2; ++mt) {
                int rA = r0 + mt * 16 + g;
                float ml0 = -3.0e38f, ml1 = -3.0e38f;
                #pragma unroll
                for (int ntl = 0; ntl < 4; ++ntl) {
                    int gc = ct * 128 + (ntb + ntl) * 8 + 2 * tig;
                    float2 mf = *(const float2*)&smf[MFL_W + gc];
                    float2 b0 = *(const float2*)(bias0 + (size_t)rA * SEQ + gc);
                    float2 b1 = *(const float2*)(bias0 + (size_t)(rA + 8) * SEQ + gc);
                    float s0 = (mf.x != 0.0f) ? sacc[mt][ntl][0] + b0.x : -1e9f;
                    float s1 = (mf.y != 0.0f) ? sacc[mt][ntl][1] + b0.y : -1e9f;
                    float s2v = (mf.x != 0.0f) ? sacc[mt][ntl][2] + b1.x : -1e9f;
                    float s3 = (mf.y != 0.0f) ? sacc[mt][ntl][3] + b1.y : -1e9f;
                    sacc[mt][ntl][0] = s0; sacc[mt][ntl][1] = s1;
                    sacc[mt][ntl][2] = s2v; sacc[mt][ntl][3] = s3;
                    ml0 = fmaxf(ml0, fmaxf(s0, s1));
                    ml1 = fmaxf(ml1, fmaxf(s2v, s3));
                }
                float mn0 = fmaxf(om[mt][0], ml0);
                float mn1 = fmaxf(om[mt][1], ml1);
                // unify across tig lanes (same row)
                mn0 = fmaxf(mn0, __shfl_xor_sync(~0u, mn0, 1));
                mn0 = fmaxf(mn0, __shfl_xor_sync(~0u, mn0, 2));
                mn1 = fmaxf(mn1, __shfl_xor_sync(~0u, mn1, 1));
                mn1 = fmaxf(mn1, __shfl_xor_sync(~0u, mn1, 2));
                float a0 = 0.0f, a1 = 0.0f;
                #pragma unroll
                for (int ntl = 0; ntl < 4; ++ntl) {
                    int gc = ct * 128 + (ntb + ntl) * 8 + 2 * tig;
                    float e0 = __expf(sacc[mt][ntl][0] - mn0);
                    float e1 = __expf(sacc[mt][ntl][1] - mn0);
                    float e2 = __expf(sacc[mt][ntl][2] - mn1);
                    float e3 = __expf(sacc[mt][ntl][3] - mn1);
                    *(float2*)(attn0 + (size_t)rA * SEQ + gc)       = make_float2(e0, e1);
                    *(float2*)(attn0 + (size_t)(rA + 8) * SEQ + gc) = make_float2(e2, e3);
                    a0 += e0 + e1;
                    a1 += e2 + e3;
                }
                ol[mt][0] = ol[mt][0] * __expf(om[mt][0] - mn0) + a0;  om[mt][0] = mn0;
                ol[mt][1] = ol[mt][1] * __expf(om[mt][1] - mn1) + a1;  om[mt][1] = mn1;
                if (tig == 0) {
                    smf[CSM_W + cidx * 128 + rA]     = mn0;
                    smf[CSM_W + cidx * 128 + rA + 8] = mn1;
                }
            }
        }
    }

    // ---- merge l across tig (m already uniform), then the two wc slots ----
    #pragma unroll
    for (int mt = 0; mt < 2; ++mt)
        #pragma unroll
        for (int h = 0; h < 2; ++h) {
            float l = ol[mt][h];
            l += __shfl_xor_sync(~0u, l, 1);
            l += __shfl_xor_sync(~0u, l, 2);
            if (tig == 0) {
                int row = r0 + mt * 16 + g + 8 * h;
                *(float2*)&smf[RED_W + (wc * 128 + row) * 2] = make_float2(om[mt][h], l);
            }
        }
    __syncthreads();
    if (tid < 128) {
        float2 a = *(const float2*)&smf[RED_W + tid * 2];
        float2 c = *(const float2*)&smf[RED_W + (128 + tid) * 2];
        float mn = fmaxf(a.x, c.x);
        float l  = a.y * __expf(a.x - mn) + c.y * __expf(c.x - mn);
        *(float2*)&smf[RST_W + tid * 2] = make_float2(mn, 1.0f / l);
    }
    __syncthreads();

    // ---- transform csm: m_c -> exp(m_c - m_f) / l  (the per-group corr) ----
    for (int i = tid; i < 32 * 128; i += TPB) {
        int row = i & 127;
        float2 rsv = *(const float2*)&smf[RST_W + row * 2];
        smf[CSM_W + i] = __expf(smf[CSM_W + i] - rsv.x) * rsv.y;
    }
    __syncthreads();

    // ========== Pass B: p = e * corr -> attn; O = P @ V (M=16 per warp) =====
    const int r0b = w * 16;

    float oacc[8][4];
    #pragma unroll
    for (int nt = 0; nt < 8; ++nt)
        #pragma unroll
        for (int r2 = 0; r2 < 4; ++r2) oacc[nt][r2] = 0.0f;

    for (int ct = 0; ct < NCHUNK; ++ct) {
        __syncthreads();
        // stage V chunk: direct B-frag build, 1 STS.128 per task
        #pragma unroll
        for (int i = 0; i < 8; ++i) {
            int task = i * TPB + tid;
            int lt = task & 31, ks = (task >> 5) & 7, nt = task >> 8;
            int gt = lt >> 2, tt = lt & 3;
            int d  = nt * 8 + gt;
            const float* vp = vbase + (size_t)(ct * 128 + ks * 16 + 2 * tt) * DH + d;
            float v0 = vp[0];
            float v1 = vp[DH];
            float v8 = vp[8 * DH];
            float v9 = vp[9 * DH];
            float h0 = hhi(v0), h1 = hhi(v1), h8 = hhi(v8), h9 = hhi(v9);
            uint4 u;
            u.x = hpack(h0, h1);
            u.y = hpack(h8, h9);
            u.z = hpack(v0 - h0, v1 - h1);
            u.w = hpack(v8 - h8, v9 - h9);
            *(uint4*)&smw[KVF_W + (uint32_t)(((nt * 8 + ks) * 32 + lt) * 4)] = u;
        }
        __syncthreads();

        #pragma unroll
        for (int ks = 0; ks < 8; ++ks) {
            const int cidx = ct * 4 + (ks >> 1);
            const float f0 = smf[CSM_W + cidx * 128 + r0b + g];
            const float f1 = smf[CSM_W + cidx * 128 + r0b + g + 8];
            float* ar0 = attn0 + (size_t)(r0b + g) * SEQ + ct * 128 + ks * 16;
            float* ar1 = ar0 + (size_t)8 * SEQ;
            float2 s0 = *(const float2*)(ar0 + 2 * tig);
            float2 s1 = *(const float2*)(ar1 + 2 * tig);
            float2 s2 = *(const float2*)(ar0 + 2 * tig + 8);
            float2 s3 = *(const float2*)(ar1 + 2 * tig + 8);
            float2 p0, p1, p2, p3;
            p0.x = s0.x * f0;  p0.y = s0.y * f0;
            p1.x = s1.x * f1;  p1.y = s1.y * f1;
            p2.x = s2.x * f0;  p2.y = s2.y * f0;
            p3.x = s3.x * f1;  p3.y = s3.y * f1;
            *(float2*)(ar0 + 2 * tig)     = p0;
            *(float2*)(ar1 + 2 * tig)     = p1;
            *(float2*)(ar0 + 2 * tig + 8) = p2;
            *(float2*)(ar1 + 2 * tig + 8) = p3;
            uint32_t a0 = hpack(hhi(p0.x), hhi(p0.y));
            uint32_t a1 = hpack(hhi(p1.x), hhi(p1.y));
            uint32_t a2 = hpack(hhi(p2.x), hhi(p2.y));
            uint32_t a3 = hpack(hhi(p3.x), hhi(p3.y));
            #pragma unroll
            for (int nt = 0; nt < 8; ++nt) {
                uint4 bb = *(const uint4*)&smw[KVF_W +
                    (uint32_t)(((nt * 8 + ks) * 32 + lane) * 4)];
                mma_f16(oacc[nt], a0, a1, a2, a3, bb.x, bb.y);
                mma_f16(oacc[nt], a0, a1, a2, a3, bb.z, bb.w);
            }
        }
    }

    // ---- write O directly ----
    {
        float* orow0 = out + ((size_t)bh * SEQ + q0 + r0b + g) * DH;
        float* orow1 = orow0 + (size_t)8 * DH;
        #pragma unroll
        for (int nt = 0; nt < 8; ++nt) {
            int col = nt * 8 + 2 * tig;
            *(float2*)(orow0 + col) = make_float2(oacc[nt][0], oacc[nt][1]);
            *(float2*)(orow1 + col) = make_float2(oacc[nt][2], oacc[nt][3]);
        }
    }
}

extern "C" void kernel_launch(void* const* d_in, const int* in_sizes, int n_in,
                              void* d_out, int out_size)
{
    (void)in_sizes; (void)n_in; (void)out_size;
    const float* q        = (const float*)d_in[0];
    const float* k        = (const float*)d_in[1];
    const float* v        = (const float*)d_in[2];
    const float* add_attn = (const float*)d_in[3];
    const int*   mask     = (const int*)d_in[4];

    float* out  = (float*)d_out;
    float* attn = out + (size_t)4 * 16 * 1024 * 64;

    cudaFuncSetAttribute(attn_fp16_kernel,
                         cudaFuncAttributeMaxDynamicSharedMemorySize, SM_BYTES);

    dim3 grid(SEQ / BM, 4 * 16);   // (8, 64)
    attn_fp16_kernel<<<grid, TPB, SM_BYTES>>>(q, k, v, add_attn, mask, out, attn);
}